// round 1
// baseline (speedup 1.0000x reference)
#include <cuda_runtime.h>

#define BB  32
#define CC  16
#define HH  256
#define WWID 256
#define PP  144
#define HID 128
#define LL  16384   // 128*128 positions
#define TM  64      // positions per block

// Scratch for out_p: (B, L, P) fp32 = 302 MB (device global, zero-init bss)
__device__ float g_outp[(size_t)BB * LL * PP];

// ---------------------------------------------------------------------------
// Kernel A: fused patch-gather + MLP (144 -> relu(128) -> 144), writes out_p
// Block: 256 threads, handles 64 consecutive positions (same ho row)
// smem: W (18432 fl, reused for W1 then W2) | patches 64x145 | H 64x132
// ---------------------------------------------------------------------------
__global__ __launch_bounds__(256, 1)
void mlp_kernel(const float* __restrict__ x, const float* __restrict__ W1,
                const float* __restrict__ b1, const float* __restrict__ W2,
                const float* __restrict__ b2) {
    extern __shared__ float sm[];
    float* Ws = sm;                    // 144*128 = 18432 floats (W1, then W2)
    float* Ps = sm + 18432;            // 64*145  = 9280
    float* Hs = sm + 18432 + 9280;     // 64*132  = 8448

    const int tid  = threadIdx.x;
    const int blk  = blockIdx.x;
    const int b    = blk >> 8;         // 256 tiles per batch image
    const int tile = blk & 255;
    const int l0   = tile * TM;
    const int ho   = l0 >> 7;          // 64 | 128 -> whole tile shares ho
    const int wo0  = l0 & 127;

    // ---- stage W1 into smem (4608 float4, 18 per thread) ----
    {
        const float4* src = (const float4*)W1;
        float4* dst = (float4*)Ws;
        #pragma unroll
        for (int i = 0; i < 18; i++) dst[tid + i * 256] = src[tid + i * 256];
    }
    // ---- gather patches with reflect padding ----
    const float* xb = x + (size_t)b * CC * HH * WWID;
    for (int e = tid; e < TM * PP; e += 256) {
        int pos = e / PP;
        int p   = e - pos * PP;
        int c   = p / 9;
        int r   = p - c * 9;
        int kh  = r / 3, kw = r - kh * 3;
        int wo  = wo0 + pos;
        int ii  = 2 * ho + kh - 1;      // original coords (pad=1 removed)
        int jj  = 2 * wo + kw - 1;
        ii = (ii < 0) ? -ii : ((ii >= HH)   ? 2 * HH   - 2 - ii : ii);
        jj = (jj < 0) ? -jj : ((jj >= WWID) ? 2 * WWID - 2 - jj : jj);
        Ps[pos * 145 + p] = xb[(c * HH + ii) * WWID + jj];
    }
    __syncthreads();

    const int tx = tid & 15;   // 16 groups over HID (8 each) / over P (9 each)
    const int ty = tid >> 4;   // 16 groups over positions (4 each)

    // ---- phase 1: H = relu(P @ W1 + b1) ----
    float acc[4][8];
    #pragma unroll
    for (int i = 0; i < 4; i++)
        #pragma unroll
        for (int j = 0; j < 8; j++) acc[i][j] = 0.f;

    #pragma unroll 4
    for (int k = 0; k < PP; k++) {
        float av[4];
        #pragma unroll
        for (int i = 0; i < 4; i++) av[i] = Ps[(ty * 4 + i) * 145 + k];
        const float4 w0 = *(const float4*)&Ws[k * HID + tx * 8];
        const float4 w1 = *(const float4*)&Ws[k * HID + tx * 8 + 4];
        const float bv[8] = {w0.x, w0.y, w0.z, w0.w, w1.x, w1.y, w1.z, w1.w};
        #pragma unroll
        for (int i = 0; i < 4; i++)
            #pragma unroll
            for (int j = 0; j < 8; j++) acc[i][j] += av[i] * bv[j];
    }
    #pragma unroll
    for (int j = 0; j < 8; j++) {
        float bias = b1[tx * 8 + j];
        #pragma unroll
        for (int i = 0; i < 4; i++) {
            float v = acc[i][j] + bias;
            Hs[(ty * 4 + i) * 132 + tx * 8 + j] = v > 0.f ? v : 0.f;
        }
    }
    __syncthreads();   // phase-1 reads of Ws done; Hs complete

    // ---- stage W2 into smem (overwrites W1) ----
    {
        const float4* src = (const float4*)W2;
        float4* dst = (float4*)Ws;
        #pragma unroll
        for (int i = 0; i < 18; i++) dst[tid + i * 256] = src[tid + i * 256];
    }
    __syncthreads();

    // ---- phase 2: out = H @ W2 + b2 ----
    float acc2[4][9];
    #pragma unroll
    for (int i = 0; i < 4; i++)
        #pragma unroll
        for (int j = 0; j < 9; j++) acc2[i][j] = 0.f;

    #pragma unroll 2
    for (int k = 0; k < HID; k++) {
        float av[4];
        #pragma unroll
        for (int i = 0; i < 4; i++) av[i] = Hs[(ty * 4 + i) * 132 + k];
        float bv[9];
        #pragma unroll
        for (int j = 0; j < 9; j++) bv[j] = Ws[k * PP + tx * 9 + j];
        #pragma unroll
        for (int i = 0; i < 4; i++)
            #pragma unroll
            for (int j = 0; j < 9; j++) acc2[i][j] += av[i] * bv[j];
    }

    float* outb = g_outp + ((size_t)b * LL + l0) * PP;
    #pragma unroll
    for (int i = 0; i < 4; i++) {
        int pos = ty * 4 + i;
        #pragma unroll
        for (int j = 0; j < 9; j++) {
            int o = tx * 9 + j;
            outb[(size_t)pos * PP + o] = acc2[i][j] + b2[o];
        }
    }
}

// ---------------------------------------------------------------------------
// Kernel B: gather-fold + count-normalize + channel mix + softmax + modulate
// One thread per output pixel. grid = B*256 (padded rows 1..256), 256 thr (cols)
// ---------------------------------------------------------------------------
__global__ __launch_bounds__(256)
void fold_softmax_kernel(const float* __restrict__ Wc, const float* __restrict__ bc,
                         float* __restrict__ out) {
    __shared__ float sWc[256];
    __shared__ float sbc[16];
    int tid = threadIdx.x;
    sWc[tid] = Wc[tid];
    if (tid < 16) sbc[tid] = bc[tid];
    __syncthreads();

    const int b = blockIdx.x >> 8;
    const int i = (blockIdx.x & 255) + 1;   // padded row in [1,256]
    const int j = tid + 1;                  // padded col in [1,256]

    // contributors: kh with (i-kh) even and ho=(i-kh)/2 in [0,127]
    int khA[2], hoA[2], nh = 0;
    #pragma unroll
    for (int kh = 0; kh < 3; kh++) {
        int t = i - kh;
        if (t >= 0 && t <= 254 && !(t & 1)) { khA[nh] = kh; hoA[nh] = t >> 1; nh++; }
    }
    int kwA[2], woA[2], nw = 0;
    #pragma unroll
    for (int kw = 0; kw < 3; kw++) {
        int t = j - kw;
        if (t >= 0 && t <= 254 && !(t & 1)) { kwA[nw] = kw; woA[nw] = t >> 1; nw++; }
    }

    float nrm[16];
    #pragma unroll
    for (int c = 0; c < 16; c++) nrm[c] = 0.f;

    for (int a = 0; a < nh; a++)
        for (int d = 0; d < nw; d++) {
            const float* rec = g_outp
                + ((size_t)b * LL + hoA[a] * 128 + woA[d]) * PP
                + khA[a] * 3 + kwA[d];
            #pragma unroll
            for (int c = 0; c < 16; c++) nrm[c] += rec[c * 9];
        }

    const float inv = 1.f / ((float)(nh * nw) + 1e-6f);
    #pragma unroll
    for (int c = 0; c < 16; c++) nrm[c] *= inv;

    float logit[16];
    #pragma unroll
    for (int o = 0; o < 16; o++) {
        float s = sbc[o];
        #pragma unroll
        for (int c = 0; c < 16; c++) s += sWc[o * 16 + c] * nrm[c];
        logit[o] = s;
    }
    float m = logit[0];
    #pragma unroll
    for (int o = 1; o < 16; o++) m = fmaxf(m, logit[o]);
    float e[16], sum = 0.f;
    #pragma unroll
    for (int o = 0; o < 16; o++) { e[o] = __expf(logit[o] - m); sum += e[o]; }
    const float rs = 1.f / sum;

    float* ob = out + (size_t)b * CC * HH * WWID + (size_t)(i - 1) * WWID + (j - 1);
    #pragma unroll
    for (int c = 0; c < 16; c++) ob[(size_t)c * HH * WWID] = nrm[c] * e[c] * rs;
}

// ---------------------------------------------------------------------------
extern "C" void kernel_launch(void* const* d_in, const int* in_sizes, int n_in,
                              void* d_out, int out_size) {
    const float* x  = (const float*)d_in[0];
    const float* W1 = (const float*)d_in[1];
    const float* b1 = (const float*)d_in[2];
    const float* W2 = (const float*)d_in[3];
    const float* b2 = (const float*)d_in[4];
    const float* Wc = (const float*)d_in[5];
    const float* bc = (const float*)d_in[6];
    float* out = (float*)d_out;

    const int smem = (18432 + 64 * 145 + 64 * 132) * (int)sizeof(float); // 144640 B
    cudaFuncSetAttribute(mlp_kernel, cudaFuncAttributeMaxDynamicSharedMemorySize, smem);

    mlp_kernel<<<BB * 256, 256, smem>>>(x, W1, b1, W2, b2);
    fold_softmax_kernel<<<BB * 256, 256>>>(Wc, bc, out);
}

// round 2
// speedup vs baseline: 1.0571x; 1.0571x over previous
#include <cuda_runtime.h>

#define BB  32
#define CC  16
#define HH  256
#define WWID 256
#define PP  144
#define HID 128
#define LL  16384   // 128*128 positions
#define TM  64      // positions per block

// Scratch for out_p: (B, L, P) fp32 = 302 MB (device global, zero-init bss)
__device__ float g_outp[(size_t)BB * LL * PP];

typedef unsigned long long u64;

__device__ __forceinline__ u64 bcast2(float a) {
    u64 r; asm("mov.b64 %0, {%1, %1};" : "=l"(r) : "f"(a)); return r;
}
__device__ __forceinline__ u64 pack2(float a, float b) {
    u64 r; asm("mov.b64 %0, {%1, %2};" : "=l"(r) : "f"(a), "f"(b)); return r;
}
__device__ __forceinline__ void fma2(u64& d, u64 a, u64 b) {
    asm("fma.rn.f32x2 %0, %1, %2, %0;" : "+l"(d) : "l"(a), "l"(b));
}
__device__ __forceinline__ float2 unpack2(u64 a) {
    float2 f; asm("mov.b64 {%0, %1}, %2;" : "=f"(f.x), "=f"(f.y) : "l"(a)); return f;
}

// smem float offsets
#define WS_OFF 0
#define WS_FL  24576              // max(144*128=18432, 128*192=24576)
#define PS_OFF WS_FL              // 64 x 148
#define PS_STR 148
#define HS_OFF (WS_FL + 64*148)   // 64 x 136
#define HS_STR 136
#define SMEM_FL (WS_FL + 64*148 + 64*136)   // 42752 floats = 171008 B

// ---------------------------------------------------------------------------
// Kernel A: fused patch-gather + MLP (144 -> relu(128) -> 144) via fma.f32x2
// Block: 256 threads, 64 consecutive positions (same ho row)
// ---------------------------------------------------------------------------
__global__ __launch_bounds__(256, 1)
void mlp_kernel(const float* __restrict__ x, const float* __restrict__ W1,
                const float* __restrict__ b1, const float* __restrict__ W2,
                const float* __restrict__ b2) {
    extern __shared__ float sm[];
    float* Ws = sm + WS_OFF;
    float* Ps = sm + PS_OFF;
    float* Hs = sm + HS_OFF;

    const int tid  = threadIdx.x;
    const int blk  = blockIdx.x;
    const int b    = blk >> 8;
    const int tile = blk & 255;
    const int l0   = tile * TM;
    const int ho   = l0 >> 7;
    const int wo0  = l0 & 127;

    // ---- stage W1 into smem (4608 float4, 18 per thread) ----
    {
        const float4* src = (const float4*)W1;
        float4* dst = (float4*)Ws;
        #pragma unroll
        for (int i = 0; i < 18; i++) dst[tid + i * 256] = src[tid + i * 256];
    }
    // ---- gather patches with reflect padding ----
    const float* xb = x + (size_t)b * CC * HH * WWID;
    for (int e = tid; e < TM * PP; e += 256) {
        int pos = e / PP;
        int p   = e - pos * PP;
        int c   = p / 9;
        int r   = p - c * 9;
        int kh  = r / 3, kw = r - kh * 3;
        int wo  = wo0 + pos;
        int ii  = 2 * ho + kh - 1;
        int jj  = 2 * wo + kw - 1;
        ii = (ii < 0) ? -ii : ((ii >= HH)   ? 2 * HH   - 2 - ii : ii);
        jj = (jj < 0) ? -jj : ((jj >= WWID) ? 2 * WWID - 2 - jj : jj);
        Ps[pos * PS_STR + p] = xb[(c * HH + ii) * WWID + jj];
    }
    __syncthreads();

    const int tx = tid & 15;   // 16 groups: 8 HID cols (phase1) / 9 P cols (phase2)
    const int ty = tid >> 4;   // 16 groups of 4 positions

    // ---- phase 1: H = relu(P @ W1 + b1), acc pairs along columns ----
    u64 acc[4][4];
    #pragma unroll
    for (int i = 0; i < 4; i++)
        #pragma unroll
        for (int j = 0; j < 4; j++) acc[i][j] = 0ULL;

    for (int k0 = 0; k0 < PP; k0 += 4) {
        float4 a4[4];
        #pragma unroll
        for (int i = 0; i < 4; i++)
            a4[i] = *(const float4*)&Ps[(ty * 4 + i) * PS_STR + k0];
        #pragma unroll
        for (int kk = 0; kk < 4; kk++) {
            const float4 w0 = *(const float4*)&Ws[(k0 + kk) * HID + tx * 8];
            const float4 w1 = *(const float4*)&Ws[(k0 + kk) * HID + tx * 8 + 4];
            u64 bp[4];
            bp[0] = pack2(w0.x, w0.y); bp[1] = pack2(w0.z, w0.w);
            bp[2] = pack2(w1.x, w1.y); bp[3] = pack2(w1.z, w1.w);
            #pragma unroll
            for (int i = 0; i < 4; i++) {
                const float av = ((const float*)&a4[i])[kk];
                const u64 ab = bcast2(av);
                #pragma unroll
                for (int j = 0; j < 4; j++) fma2(acc[i][j], ab, bp[j]);
            }
        }
    }
    {
        float bias[8];
        #pragma unroll
        for (int j = 0; j < 8; j++) bias[j] = b1[tx * 8 + j];
        #pragma unroll
        for (int i = 0; i < 4; i++) {
            float* hrow = &Hs[(ty * 4 + i) * HS_STR + tx * 8];
            #pragma unroll
            for (int j = 0; j < 4; j++) {
                float2 v = unpack2(acc[i][j]);
                float v0 = v.x + bias[2 * j];
                float v1 = v.y + bias[2 * j + 1];
                hrow[2 * j]     = v0 > 0.f ? v0 : 0.f;
                hrow[2 * j + 1] = v1 > 0.f ? v1 : 0.f;
            }
        }
    }
    __syncthreads();   // phase-1 reads of Ws done; Hs complete

    // ---- stage W2 into smem, padded per-thread-group layout [k][g*12+j] ----
    for (int idx = tid; idx < HID * PP; idx += 256) {
        int k = idx / PP;
        int p = idx - k * PP;
        int g = p / 9;
        int j = p - g * 9;
        Ws[k * 192 + g * 12 + j] = W2[idx];
    }
    __syncthreads();

    // ---- phase 2: out = H @ W2 + b2 (9 cols = 4 pairs + 1 scalar) ----
    u64   acc2[4][4];
    float accs[4];
    #pragma unroll
    for (int i = 0; i < 4; i++) {
        accs[i] = 0.f;
        #pragma unroll
        for (int j = 0; j < 4; j++) acc2[i][j] = 0ULL;
    }

    for (int k0 = 0; k0 < HID; k0 += 4) {
        float4 h4[4];
        #pragma unroll
        for (int i = 0; i < 4; i++)
            h4[i] = *(const float4*)&Hs[(ty * 4 + i) * HS_STR + k0];
        #pragma unroll
        for (int kk = 0; kk < 4; kk++) {
            const float* wr = &Ws[(k0 + kk) * 192 + tx * 12];
            const float4 v0 = *(const float4*)wr;
            const float4 v1 = *(const float4*)(wr + 4);
            const float  v8 = wr[8];
            u64 bp[4];
            bp[0] = pack2(v0.x, v0.y); bp[1] = pack2(v0.z, v0.w);
            bp[2] = pack2(v1.x, v1.y); bp[3] = pack2(v1.z, v1.w);
            #pragma unroll
            for (int i = 0; i < 4; i++) {
                const float av = ((const float*)&h4[i])[kk];
                const u64 ab = bcast2(av);
                #pragma unroll
                for (int j = 0; j < 4; j++) fma2(acc2[i][j], ab, bp[j]);
                accs[i] = fmaf(av, v8, accs[i]);
            }
        }
    }

    float* outb = g_outp + ((size_t)b * LL + l0) * PP;
    float bias2[9];
    #pragma unroll
    for (int j = 0; j < 9; j++) bias2[j] = b2[tx * 9 + j];
    #pragma unroll
    for (int i = 0; i < 4; i++) {
        float* orow = outb + (size_t)(ty * 4 + i) * PP + tx * 9;
        #pragma unroll
        for (int j = 0; j < 4; j++) {
            float2 v = unpack2(acc2[i][j]);
            orow[2 * j]     = v.x + bias2[2 * j];
            orow[2 * j + 1] = v.y + bias2[2 * j + 1];
        }
        orow[8] = accs[i] + bias2[8];
    }
}

// ---------------------------------------------------------------------------
// Kernel B: gather-fold + count-normalize + channel mix + softmax + modulate
// ---------------------------------------------------------------------------
__global__ __launch_bounds__(256)
void fold_softmax_kernel(const float* __restrict__ Wc, const float* __restrict__ bc,
                         float* __restrict__ out) {
    __shared__ float sWc[256];
    __shared__ float sbc[16];
    int tid = threadIdx.x;
    sWc[tid] = Wc[tid];
    if (tid < 16) sbc[tid] = bc[tid];
    __syncthreads();

    const int b = blockIdx.x >> 8;
    const int i = (blockIdx.x & 255) + 1;   // padded row in [1,256]
    const int j = tid + 1;                  // padded col in [1,256]

    int khA[2], hoA[2], nh = 0;
    #pragma unroll
    for (int kh = 0; kh < 3; kh++) {
        int t = i - kh;
        if (t >= 0 && t <= 254 && !(t & 1)) { khA[nh] = kh; hoA[nh] = t >> 1; nh++; }
    }
    int kwA[2], woA[2], nw = 0;
    #pragma unroll
    for (int kw = 0; kw < 3; kw++) {
        int t = j - kw;
        if (t >= 0 && t <= 254 && !(t & 1)) { kwA[nw] = kw; woA[nw] = t >> 1; nw++; }
    }

    float nrm[16];
    #pragma unroll
    for (int c = 0; c < 16; c++) nrm[c] = 0.f;

    for (int a = 0; a < nh; a++)
        for (int d = 0; d < nw; d++) {
            const float* rec = g_outp
                + ((size_t)b * LL + hoA[a] * 128 + woA[d]) * PP
                + khA[a] * 3 + kwA[d];
            #pragma unroll
            for (int c = 0; c < 16; c++) nrm[c] += rec[c * 9];
        }

    const float inv = 1.f / ((float)(nh * nw) + 1e-6f);
    #pragma unroll
    for (int c = 0; c < 16; c++) nrm[c] *= inv;

    float logit[16];
    #pragma unroll
    for (int o = 0; o < 16; o++) {
        float s = sbc[o];
        #pragma unroll
        for (int c = 0; c < 16; c++) s += sWc[o * 16 + c] * nrm[c];
        logit[o] = s;
    }
    float m = logit[0];
    #pragma unroll
    for (int o = 1; o < 16; o++) m = fmaxf(m, logit[o]);
    float e[16], sum = 0.f;
    #pragma unroll
    for (int o = 0; o < 16; o++) { e[o] = __expf(logit[o] - m); sum += e[o]; }
    const float rs = 1.f / sum;

    float* ob = out + (size_t)b * CC * HH * WWID + (size_t)(i - 1) * WWID + (j - 1);
    #pragma unroll
    for (int c = 0; c < 16; c++) ob[(size_t)c * HH * WWID] = nrm[c] * e[c] * rs;
}

// ---------------------------------------------------------------------------
extern "C" void kernel_launch(void* const* d_in, const int* in_sizes, int n_in,
                              void* d_out, int out_size) {
    const float* x  = (const float*)d_in[0];
    const float* W1 = (const float*)d_in[1];
    const float* b1 = (const float*)d_in[2];
    const float* W2 = (const float*)d_in[3];
    const float* b2 = (const float*)d_in[4];
    const float* Wc = (const float*)d_in[5];
    const float* bc = (const float*)d_in[6];
    float* out = (float*)d_out;

    const int smem = SMEM_FL * (int)sizeof(float); // 171008 B
    cudaFuncSetAttribute(mlp_kernel, cudaFuncAttributeMaxDynamicSharedMemorySize, smem);

    mlp_kernel<<<BB * 256, 256, smem>>>(x, W1, b1, W2, b2);
    fold_softmax_kernel<<<BB * 256, 256>>>(Wc, bc, out);
}

// round 4
// speedup vs baseline: 2.1962x; 2.0776x over previous
#include <cuda_runtime.h>
#include <cuda_bf16.h>
#include <cstdint>

#define BB   32
#define CC   16
#define HH   256
#define WWID 256
#define PP   144
#define HID  128
#define LL   16384

// Scratch for out_p: (B, L, P) fp32 = 302 MB
__device__ float g_outp[(size_t)BB * LL * PP];

// ---------------- smem byte offsets ----------------
#define OFF_B1  0                     // 128 floats
#define OFF_B2  512                   // 144 floats (ends 1088)
#define OFF_AHI 1152
#define SZ_A    38912                 // 128 rows * 152 * 2B
#define OFF_ALO (OFF_AHI + SZ_A)
#define OFF_BHI (OFF_ALO + SZ_A)
#define SZ_B    39168                 // max(128*152*2, 144*136*2)
#define OFF_BLO (OFF_BHI + SZ_B)
#define SMEM_TOT (OFF_BLO + SZ_B)     // 157312 B
#define AS1 152                       // bf16 elems per row, 304B (19*16B -> conflict-free ldmatrix)
#define AS2 136                       // 272B (17*16B)

// ---------------- helpers ----------------
__device__ __forceinline__ uint32_t smem_u32(const void* p) {
    uint32_t a;
    asm("{ .reg .u64 t; cvta.to.shared.u64 t, %1; cvt.u32.u64 %0, t; }" : "=r"(a) : "l"(p));
    return a;
}
__device__ __forceinline__ void ldsm4(uint32_t* r, uint32_t a) {
    asm volatile("ldmatrix.sync.aligned.m8n8.x4.shared.b16 {%0,%1,%2,%3}, [%4];"
                 : "=r"(r[0]), "=r"(r[1]), "=r"(r[2]), "=r"(r[3]) : "r"(a));
}
__device__ __forceinline__ void ldsm2(uint32_t* r, uint32_t a) {
    asm volatile("ldmatrix.sync.aligned.m8n8.x2.shared.b16 {%0,%1}, [%2];"
                 : "=r"(r[0]), "=r"(r[1]) : "r"(a));
}
__device__ __forceinline__ void mma_bf16(float* d, const uint32_t* a, uint32_t b0, uint32_t b1) {
    asm volatile("mma.sync.aligned.m16n8k16.row.col.f32.bf16.bf16.f32 "
                 "{%0,%1,%2,%3}, {%4,%5,%6,%7}, {%8,%9}, {%0,%1,%2,%3};"
                 : "+f"(d[0]), "+f"(d[1]), "+f"(d[2]), "+f"(d[3])
                 : "r"(a[0]), "r"(a[1]), "r"(a[2]), "r"(a[3]), "r"(b0), "r"(b1));
}
__device__ __forceinline__ uint32_t split_pack(float v0, float v1, uint32_t& lo) {
    __nv_bfloat16 h0 = __float2bfloat16(v0);
    __nv_bfloat16 h1 = __float2bfloat16(v1);
    __nv_bfloat16 l0 = __float2bfloat16(v0 - __bfloat162float(h0));
    __nv_bfloat16 l1 = __float2bfloat16(v1 - __bfloat162float(h1));
    lo = (uint32_t)*(uint16_t*)&l0 | ((uint32_t)*(uint16_t*)&l1 << 16);
    return (uint32_t)*(uint16_t*)&h0 | ((uint32_t)*(uint16_t*)&h1 << 16);
}
__device__ __forceinline__ void split_sts(char* base_hi, uint32_t off, float v) {
    __nv_bfloat16 h = __float2bfloat16(v);
    __nv_bfloat16 l = __float2bfloat16(v - __bfloat162float(h));
    *(uint16_t*)(base_hi + off) = *(uint16_t*)&h;
    *(uint16_t*)(base_hi + SZ_B + off) = *(uint16_t*)&l;   // B region: lo at +SZ_B
}

// ---------------------------------------------------------------------------
// Kernel A: bf16-split MLP via mma.sync (HMMA). One CTA = one (b, ho) row.
// ---------------------------------------------------------------------------
__global__ __launch_bounds__(256, 1)
void mlp_mma(const float* __restrict__ x, const float* __restrict__ W1,
             const float* __restrict__ b1, const float* __restrict__ W2,
             const float* __restrict__ b2) {
    extern __shared__ char smem[];
    const uint32_t sb = smem_u32(smem);
    const int tid = threadIdx.x;
    const int wid = tid >> 5, lid = tid & 31;
    const int b  = blockIdx.x >> 7;
    const int ho = blockIdx.x & 127;

    float* b1s = (float*)(smem + OFF_B1);
    float* b2s = (float*)(smem + OFF_B2);
    if (tid < 128) b1s[tid] = b1[tid];
    if (tid < 144) b2s[tid] = b2[tid];

    // ---- gather patches -> A1 hi/lo, row=pos (0..127), col=p (0..143) ----
    {
        const int pos  = tid >> 1;
        const int half = tid & 1;
        const float* xb = x + (size_t)b * CC * HH * WWID;
        #pragma unroll 4
        for (int i = 0; i < 36; i++) {
            int p0 = (half * 36 + i) * 2;
            float v[2];
            #pragma unroll
            for (int q = 0; q < 2; q++) {
                int p = p0 + q;
                int c = p / 9, rr = p - c * 9;
                int kh = rr / 3, kw = rr - kh * 3;
                int ii = 2 * ho + kh - 1;
                int jj = 2 * pos + kw - 1;
                ii = (ii < 0) ? -ii : ((ii >= HH) ? 2 * HH - 2 - ii : ii);
                jj = (jj < 0) ? -jj : ((jj >= WWID) ? 2 * WWID - 2 - jj : jj);
                v[q] = __ldg(&xb[(c * HH + ii) * WWID + jj]);
            }
            uint32_t lo, hi = split_pack(v[0], v[1], lo);
            uint32_t off = (uint32_t)(pos * AS1 + p0) * 2;
            *(uint32_t*)(smem + OFF_AHI + off) = hi;
            *(uint32_t*)(smem + OFF_ALO + off) = lo;
        }
    }
    // ---- B1 = W1^T: [n=0..127][k=0..143], stride AS1 ----
    #pragma unroll 4
    for (int i = 0; i < 72; i++) {
        int e = i * 256 + tid;           // e = k*128 + n
        int k = e >> 7, n = e & 127;
        split_sts(smem + OFF_BHI, (uint32_t)(n * AS1 + k) * 2, __ldg(&W1[e]));
    }
    __syncthreads();

    // ---- GEMM1: D1[128pos x 128hid], warp grid 4(m) x 2(n) ----
    const int wm = (wid & 3) * 32;
    const int wn = wid >> 2;
    const int g = lid >> 3, r = lid & 7;
    const int khalf = (g >> 1) * 8;

    float d1[2][8][4];
    #pragma unroll
    for (int mi = 0; mi < 2; mi++)
        #pragma unroll
        for (int nj = 0; nj < 8; nj++)
            #pragma unroll
            for (int q = 0; q < 4; q++) d1[mi][nj][q] = 0.f;

    {
        uint32_t pA[2], pB[4];
        #pragma unroll
        for (int mi = 0; mi < 2; mi++)
            pA[mi] = sb + OFF_AHI + (uint32_t)((wm + mi * 16 + (g & 1) * 8 + r) * AS1 + khalf) * 2;
        #pragma unroll
        for (int np = 0; np < 4; np++)
            pB[np] = sb + OFF_BHI + (uint32_t)((wn * 64 + np * 16 + (g & 1) * 8 + r) * AS1 + khalf) * 2;

        uint32_t a[2][4], bA[4][4], bB[4][4];
        for (int ks = 0; ks < 9; ks++) {
            const uint32_t ko = ks * 32;
            #pragma unroll
            for (int mi = 0; mi < 2; mi++) ldsm4(a[mi], pA[mi] + ko);
            #pragma unroll
            for (int np = 0; np < 4; np++) ldsm4(bA[np], pB[np] + ko);
            #pragma unroll
            for (int mi = 0; mi < 2; mi++)
                #pragma unroll
                for (int np = 0; np < 4; np++) {
                    mma_bf16(d1[mi][np * 2],     a[mi], bA[np][0], bA[np][2]);
                    mma_bf16(d1[mi][np * 2 + 1], a[mi], bA[np][1], bA[np][3]);
                }
            #pragma unroll
            for (int np = 0; np < 4; np++) ldsm4(bB[np], pB[np] + SZ_B + ko);
            #pragma unroll
            for (int mi = 0; mi < 2; mi++)
                #pragma unroll
                for (int np = 0; np < 4; np++) {
                    mma_bf16(d1[mi][np * 2],     a[mi], bB[np][0], bB[np][2]);
                    mma_bf16(d1[mi][np * 2 + 1], a[mi], bB[np][1], bB[np][3]);
                }
            #pragma unroll
            for (int mi = 0; mi < 2; mi++) ldsm4(a[mi], pA[mi] + SZ_A + ko);
            #pragma unroll
            for (int mi = 0; mi < 2; mi++)
                #pragma unroll
                for (int np = 0; np < 4; np++) {
                    mma_bf16(d1[mi][np * 2],     a[mi], bA[np][0], bA[np][2]);
                    mma_bf16(d1[mi][np * 2 + 1], a[mi], bA[np][1], bA[np][3]);
                }
        }
    }
    __syncthreads();   // everyone done reading A1/B1

    // ---- stage B2 = W2^T: [n=0..143][k=0..127], stride AS2 (overwrites B1) ----
    #pragma unroll 4
    for (int i = 0; i < 72; i++) {
        int e = i * 256 + tid;           // e = k*144 + n (coalesced)
        int k = e / 144, n = e - k * 144;
        split_sts(smem + OFF_BHI, (uint32_t)(n * AS2 + k) * 2, __ldg(&W2[e]));
    }
    // ---- epilogue1: H = relu(D1 + b1) -> A2 hi/lo (overwrites A1), stride AS2 ----
    {
        const int r0 = lid >> 2;
        const int c0 = (lid & 3) * 2;
        #pragma unroll
        for (int mi = 0; mi < 2; mi++) {
            const int rowa = wm + mi * 16 + r0;
            #pragma unroll
            for (int nj = 0; nj < 8; nj++) {
                const int col = wn * 64 + nj * 8 + c0;
                const float bb0 = b1s[col], bb1 = b1s[col + 1];
                float v0 = d1[mi][nj][0] + bb0; v0 = v0 > 0.f ? v0 : 0.f;
                float v1 = d1[mi][nj][1] + bb1; v1 = v1 > 0.f ? v1 : 0.f;
                float v2 = d1[mi][nj][2] + bb0; v2 = v2 > 0.f ? v2 : 0.f;
                float v3 = d1[mi][nj][3] + bb1; v3 = v3 > 0.f ? v3 : 0.f;
                uint32_t lo, hi;
                uint32_t offA = (uint32_t)(rowa * AS2 + col) * 2;
                hi = split_pack(v0, v1, lo);
                *(uint32_t*)(smem + OFF_AHI + offA) = hi;
                *(uint32_t*)(smem + OFF_ALO + offA) = lo;
                uint32_t offB = (uint32_t)((rowa + 8) * AS2 + col) * 2;
                hi = split_pack(v2, v3, lo);
                *(uint32_t*)(smem + OFF_AHI + offB) = hi;
                *(uint32_t*)(smem + OFF_ALO + offB) = lo;
            }
        }
    }
    __syncthreads();

    // ---- GEMM2: D2[128pos x 144], warp n-tile 72 = 4 pairs + 1 single ----
    float d2[2][9][4];
    #pragma unroll
    for (int mi = 0; mi < 2; mi++)
        #pragma unroll
        for (int nj = 0; nj < 9; nj++)
            #pragma unroll
            for (int q = 0; q < 4; q++) d2[mi][nj][q] = 0.f;

    {
        uint32_t pA[2], pB[4], pS;
        #pragma unroll
        for (int mi = 0; mi < 2; mi++)
            pA[mi] = sb + OFF_AHI + (uint32_t)((wm + mi * 16 + (g & 1) * 8 + r) * AS2 + khalf) * 2;
        #pragma unroll
        for (int np = 0; np < 4; np++)
            pB[np] = sb + OFF_BHI + (uint32_t)((wn * 72 + np * 16 + (g & 1) * 8 + r) * AS2 + khalf) * 2;
        {
            const int g2 = (lid >> 3) & 1;
            pS = sb + OFF_BHI + (uint32_t)((wn * 72 + 64 + r) * AS2 + g2 * 8) * 2;
        }

        uint32_t a[2][4], bA[4][4], bB[4][4], sA[2], sB[2];
        for (int ks = 0; ks < 8; ks++) {
            const uint32_t ko = ks * 32;
            #pragma unroll
            for (int mi = 0; mi < 2; mi++) ldsm4(a[mi], pA[mi] + ko);
            #pragma unroll
            for (int np = 0; np < 4; np++) ldsm4(bA[np], pB[np] + ko);
            ldsm2(sA, pS + ko);
            #pragma unroll
            for (int mi = 0; mi < 2; mi++) {
                #pragma unroll
                for (int np = 0; np < 4; np++) {
                    mma_bf16(d2[mi][np * 2],     a[mi], bA[np][0], bA[np][2]);
                    mma_bf16(d2[mi][np * 2 + 1], a[mi], bA[np][1], bA[np][3]);
                }
                mma_bf16(d2[mi][8], a[mi], sA[0], sA[1]);
            }
            #pragma unroll
            for (int np = 0; np < 4; np++) ldsm4(bB[np], pB[np] + SZ_B + ko);
            ldsm2(sB, pS + SZ_B + ko);
            #pragma unroll
            for (int mi = 0; mi < 2; mi++) {
                #pragma unroll
                for (int np = 0; np < 4; np++) {
                    mma_bf16(d2[mi][np * 2],     a[mi], bB[np][0], bB[np][2]);
                    mma_bf16(d2[mi][np * 2 + 1], a[mi], bB[np][1], bB[np][3]);
                }
                mma_bf16(d2[mi][8], a[mi], sB[0], sB[1]);
            }
            #pragma unroll
            for (int mi = 0; mi < 2; mi++) ldsm4(a[mi], pA[mi] + SZ_A + ko);
            #pragma unroll
            for (int mi = 0; mi < 2; mi++) {
                #pragma unroll
                for (int np = 0; np < 4; np++) {
                    mma_bf16(d2[mi][np * 2],     a[mi], bA[np][0], bA[np][2]);
                    mma_bf16(d2[mi][np * 2 + 1], a[mi], bA[np][1], bA[np][3]);
                }
                mma_bf16(d2[mi][8], a[mi], sA[0], sA[1]);
            }
        }
    }

    // ---- epilogue2: out = D2 + b2 -> g_outp ----
    {
        const int r0 = lid >> 2;
        const int c0 = (lid & 3) * 2;
        float* ob = g_outp + ((size_t)b * LL + (size_t)ho * 128) * PP;
        #pragma unroll
        for (int mi = 0; mi < 2; mi++) {
            const int rowa = wm + mi * 16 + r0;
            #pragma unroll
            for (int nj = 0; nj < 9; nj++) {
                const int col = wn * 72 + nj * 8 + c0;
                const float bb0 = b2s[col], bb1 = b2s[col + 1];
                float2 v0 = make_float2(d2[mi][nj][0] + bb0, d2[mi][nj][1] + bb1);
                float2 v1 = make_float2(d2[mi][nj][2] + bb0, d2[mi][nj][3] + bb1);
                *(float2*)&ob[(size_t)rowa * PP + col]       = v0;
                *(float2*)&ob[(size_t)(rowa + 8) * PP + col] = v1;
            }
        }
    }
}

// ---------------------------------------------------------------------------
// Kernel B: gather-fold + normalize + channel mix + softmax + modulate
// ---------------------------------------------------------------------------
__global__ __launch_bounds__(256)
void fold_softmax_kernel(const float* __restrict__ Wc, const float* __restrict__ bc,
                         float* __restrict__ out) {
    __shared__ float sWc[256];
    __shared__ float sbc[16];
    int tid = threadIdx.x;
    sWc[tid] = Wc[tid];
    if (tid < 16) sbc[tid] = bc[tid];
    __syncthreads();

    const int b = blockIdx.x >> 8;
    const int i = (blockIdx.x & 255) + 1;
    const int j = tid + 1;

    int khA[2], hoA[2], nh = 0;
    #pragma unroll
    for (int kh = 0; kh < 3; kh++) {
        int t = i - kh;
        if (t >= 0 && t <= 254 && !(t & 1)) { khA[nh] = kh; hoA[nh] = t >> 1; nh++; }
    }
    int kwA[2], woA[2], nw = 0;
    #pragma unroll
    for (int kw = 0; kw < 3; kw++) {
        int t = j - kw;
        if (t >= 0 && t <= 254 && !(t & 1)) { kwA[nw] = kw; woA[nw] = t >> 1; nw++; }
    }

    float nrm[16];
    #pragma unroll
    for (int c = 0; c < 16; c++) nrm[c] = 0.f;

    for (int a = 0; a < nh; a++)
        for (int d = 0; d < nw; d++) {
            const float* rec = g_outp
                + ((size_t)b * LL + hoA[a] * 128 + woA[d]) * PP
                + khA[a] * 3 + kwA[d];
            #pragma unroll
            for (int c = 0; c < 16; c++) nrm[c] += rec[c * 9];
        }

    const float inv = 1.f / ((float)(nh * nw) + 1e-6f);
    #pragma unroll
    for (int c = 0; c < 16; c++) nrm[c] *= inv;

    float logit[16];
    #pragma unroll
    for (int o = 0; o < 16; o++) {
        float s = sbc[o];
        #pragma unroll
        for (int c = 0; c < 16; c++) s += sWc[o * 16 + c] * nrm[c];
        logit[o] = s;
    }
    float m = logit[0];
    #pragma unroll
    for (int o = 1; o < 16; o++) m = fmaxf(m, logit[o]);
    float e[16], sum = 0.f;
    #pragma unroll
    for (int o = 0; o < 16; o++) { e[o] = __expf(logit[o] - m); sum += e[o]; }
    const float rs = 1.f / sum;

    float* ob = out + (size_t)b * CC * HH * WWID + (size_t)(i - 1) * WWID + (j - 1);
    #pragma unroll
    for (int c = 0; c < 16; c++) ob[(size_t)c * HH * WWID] = nrm[c] * e[c] * rs;
}

// ---------------------------------------------------------------------------
extern "C" void kernel_launch(void* const* d_in, const int* in_sizes, int n_in,
                              void* d_out, int out_size) {
    const float* x  = (const float*)d_in[0];
    const float* W1 = (const float*)d_in[1];
    const float* b1 = (const float*)d_in[2];
    const float* W2 = (const float*)d_in[3];
    const float* b2 = (const float*)d_in[4];
    const float* Wc = (const float*)d_in[5];
    const float* bc = (const float*)d_in[6];
    float* out = (float*)d_out;

    cudaFuncSetAttribute(mlp_mma, cudaFuncAttributeMaxDynamicSharedMemorySize, SMEM_TOT);

    mlp_mma<<<BB * 128, 256, SMEM_TOT>>>(x, W1, b1, W2, b2);
    fold_softmax_kernel<<<BB * 256, 256>>>(Wc, bc, out);
}

// round 5
// speedup vs baseline: 3.6263x; 1.6511x over previous
#include <cuda_runtime.h>
#include <cuda_bf16.h>
#include <cstdint>

#define BB   32
#define CC   16
#define HH   256
#define WWID 256
#define PP   144
#define HID  128
#define LL   16384
#define NT   8192      // tiles: B * 128 ho * 2 halves
#define NCTA 152

// Scratch for out_p: (B, L, P) fp32 = 302 MB
__device__ float g_outp[(size_t)BB * LL * PP];

// ---------------- smem byte offsets ----------------
#define OFF_B1H 0
#define OFF_B1L 38912              // 128 x 152 x 2B
#define OFF_B2H 77824
#define OFF_B2L 116992             // 144 x 136 x 2B
#define OFF_AH  156160             // 64 x 152 x 2B (A1) / 64 x 136 x 2B (A2)
#define OFF_AL  175616
#define OFF_b1  195072
#define OFF_b2  195584
#define SMEM_TOT 196160
#define AS1 152                    // 304B rows: 19*16B -> conflict-free ldmatrix
#define AS2 136                    // 272B rows: 17*16B
#define DB1 38912                  // hi->lo delta, B1
#define DB2 39168                  // hi->lo delta, B2
#define DA  19456                  // hi->lo delta, A

// ---------------- helpers ----------------
__device__ __forceinline__ uint32_t smem_u32(const void* p) {
    uint32_t a;
    asm("{ .reg .u64 t; cvta.to.shared.u64 t, %1; cvt.u32.u64 %0, t; }" : "=r"(a) : "l"(p));
    return a;
}
__device__ __forceinline__ void ldsm4(uint32_t* r, uint32_t a) {
    asm volatile("ldmatrix.sync.aligned.m8n8.x4.shared.b16 {%0,%1,%2,%3}, [%4];"
                 : "=r"(r[0]), "=r"(r[1]), "=r"(r[2]), "=r"(r[3]) : "r"(a));
}
__device__ __forceinline__ void ldsm2(uint32_t* r, uint32_t a) {
    asm volatile("ldmatrix.sync.aligned.m8n8.x2.shared.b16 {%0,%1}, [%2];"
                 : "=r"(r[0]), "=r"(r[1]) : "r"(a));
}
__device__ __forceinline__ void mma_bf16(float* d, const uint32_t* a, uint32_t b0, uint32_t b1) {
    asm volatile("mma.sync.aligned.m16n8k16.row.col.f32.bf16.bf16.f32 "
                 "{%0,%1,%2,%3}, {%4,%5,%6,%7}, {%8,%9}, {%0,%1,%2,%3};"
                 : "+f"(d[0]), "+f"(d[1]), "+f"(d[2]), "+f"(d[3])
                 : "r"(a[0]), "r"(a[1]), "r"(a[2]), "r"(a[3]), "r"(b0), "r"(b1));
}
__device__ __forceinline__ uint32_t split_pack(float v0, float v1, uint32_t& lo) {
    __nv_bfloat16 h0 = __float2bfloat16(v0);
    __nv_bfloat16 h1 = __float2bfloat16(v1);
    __nv_bfloat16 l0 = __float2bfloat16(v0 - __bfloat162float(h0));
    __nv_bfloat16 l1 = __float2bfloat16(v1 - __bfloat162float(h1));
    lo = (uint32_t)*(uint16_t*)&l0 | ((uint32_t)*(uint16_t*)&l1 << 16);
    return (uint32_t)*(uint16_t*)&h0 | ((uint32_t)*(uint16_t*)&h1 << 16);
}
__device__ __forceinline__ void split_sts(char* hi_base, uint32_t off, uint32_t lodelta, float v) {
    __nv_bfloat16 h = __float2bfloat16(v);
    __nv_bfloat16 l = __float2bfloat16(v - __bfloat162float(h));
    *(uint16_t*)(hi_base + off) = *(uint16_t*)&h;
    *(uint16_t*)(hi_base + lodelta + off) = *(uint16_t*)&l;
}
__device__ __forceinline__ int refl(int v, int n) {
    return (v < 0) ? -v : ((v >= n) ? 2 * n - 2 - v : v);
}

// ---------------------------------------------------------------------------
// Persistent MLP kernel. grid = NCTA, 256 threads. Weights staged once.
// Tile = 64 positions (b, ho, half).
// ---------------------------------------------------------------------------
__global__ __launch_bounds__(256, 1)
void mlp_persist(const float* __restrict__ x, const float* __restrict__ W1,
                 const float* __restrict__ b1, const float* __restrict__ W2,
                 const float* __restrict__ b2) {
    extern __shared__ char smem[];
    const uint32_t sb = smem_u32(smem);
    const int tid = threadIdx.x;
    const int wid = tid >> 5, lid = tid & 31;

    float* b1s = (float*)(smem + OFF_b1);
    float* b2s = (float*)(smem + OFF_b2);
    if (tid < 128) b1s[tid] = b1[tid];
    if (tid < 144) b2s[tid] = b2[tid];

    // ---- stage W1^T and W2^T (split) ONCE ----
    #pragma unroll 4
    for (int i = 0; i < 72; i++) {
        int e = i * 256 + tid;               // e = k*128 + n
        int k = e >> 7, n = e & 127;
        split_sts(smem + OFF_B1H, (uint32_t)(n * AS1 + k) * 2, DB1, __ldg(&W1[e]));
    }
    #pragma unroll 4
    for (int i = 0; i < 72; i++) {
        int e = i * 256 + tid;               // e = k*144 + n
        int k = e / 144, n = e - k * 144;
        split_sts(smem + OFF_B2H, (uint32_t)(n * AS2 + k) * 2, DB2, __ldg(&W2[e]));
    }

    // warp tiling constants
    const int wm = (wid & 3) * 16;
    const int wn = wid >> 2;
    const int g = lid >> 3, r = lid & 7;
    const int khalf = (g >> 1) * 8;
    const int arow = wm + (g & 1) * 8 + r;

    // gather mapping: pos = tid>>2 (64), quarter q = tid&3 -> p in [q*36, q*36+36)
    const int pos = tid >> 2;
    const int q   = tid & 3;
    const int pb  = q * 36;

    float xv[36];

    // ---- prefetch first tile ----
    {
        int t = blockIdx.x;
        int b = t >> 8, rem = t & 255, ho = rem >> 1, wo0 = (rem & 1) * 64;
        const float* xb = x + (size_t)b * CC * HH * WWID;
        int rw[3], cl[3];
        #pragma unroll
        for (int kk = 0; kk < 3; kk++) {
            rw[kk] = refl(2 * ho + kk - 1, HH) * WWID;
            cl[kk] = refl(2 * (wo0 + pos) + kk - 1, WWID);
        }
        #pragma unroll
        for (int i = 0; i < 36; i++) {
            int p = pb + i;
            int c = p / 9, rr = p - c * 9;
            int kh = rr / 3, kw = rr - kh * 3;
            xv[i] = __ldg(&xb[c * (HH * WWID) + rw[kh] + cl[kw]]);
        }
    }

    for (int t = blockIdx.x; t < NT; t += NCTA) {
        const int b = t >> 8, rem = t & 255, ho = rem >> 1, wo0 = (rem & 1) * 64;

        __syncthreads();   // prev GEMM2 done reading A buffer
        // ---- store A1 (split) ----
        #pragma unroll
        for (int i = 0; i < 18; i++) {
            uint32_t lo, hi = split_pack(xv[2 * i], xv[2 * i + 1], lo);
            uint32_t off = (uint32_t)(pos * AS1 + pb + 2 * i) * 2;
            *(uint32_t*)(smem + OFF_AH + off) = hi;
            *(uint32_t*)(smem + OFF_AL + off) = lo;
        }
        __syncthreads();

        // ---- GEMM1: D1[64 x 128] ----
        float d1[8][4];
        #pragma unroll
        for (int nj = 0; nj < 8; nj++)
            #pragma unroll
            for (int p = 0; p < 4; p++) d1[nj][p] = 0.f;
        {
            uint32_t pA = sb + OFF_AH + (uint32_t)(arow * AS1 + khalf) * 2;
            uint32_t pB[4];
            #pragma unroll
            for (int np = 0; np < 4; np++)
                pB[np] = sb + OFF_B1H + (uint32_t)((wn * 64 + np * 16 + (g & 1) * 8 + r) * AS1 + khalf) * 2;

            uint32_t a[4], bA[4][4], bB[4][4];
            #pragma unroll
            for (int ks = 0; ks < 9; ks++) {
                const uint32_t ko = ks * 32;
                ldsm4(a, pA + ko);
                #pragma unroll
                for (int np = 0; np < 4; np++) ldsm4(bA[np], pB[np] + ko);
                #pragma unroll
                for (int np = 0; np < 4; np++) {
                    mma_bf16(d1[np * 2],     a, bA[np][0], bA[np][2]);
                    mma_bf16(d1[np * 2 + 1], a, bA[np][1], bA[np][3]);
                }
                #pragma unroll
                for (int np = 0; np < 4; np++) ldsm4(bB[np], pB[np] + DB1 + ko);
                #pragma unroll
                for (int np = 0; np < 4; np++) {
                    mma_bf16(d1[np * 2],     a, bB[np][0], bB[np][2]);
                    mma_bf16(d1[np * 2 + 1], a, bB[np][1], bB[np][3]);
                }
                ldsm4(a, pA + DA + ko);
                #pragma unroll
                for (int np = 0; np < 4; np++) {
                    mma_bf16(d1[np * 2],     a, bA[np][0], bA[np][2]);
                    mma_bf16(d1[np * 2 + 1], a, bA[np][1], bA[np][3]);
                }
            }
        }
        __syncthreads();   // all warps done reading A1

        // ---- epi1: relu(D1+b1) split -> A2 (stride AS2) ----
        {
            const int r0 = lid >> 2;
            const int c0 = (lid & 3) * 2;
            #pragma unroll
            for (int nj = 0; nj < 8; nj++) {
                const int col = wn * 64 + nj * 8 + c0;
                const float bb0 = b1s[col], bb1 = b1s[col + 1];
                float v0 = d1[nj][0] + bb0; v0 = v0 > 0.f ? v0 : 0.f;
                float v1 = d1[nj][1] + bb1; v1 = v1 > 0.f ? v1 : 0.f;
                float v2 = d1[nj][2] + bb0; v2 = v2 > 0.f ? v2 : 0.f;
                float v3 = d1[nj][3] + bb1; v3 = v3 > 0.f ? v3 : 0.f;
                uint32_t lo, hi;
                uint32_t offA = (uint32_t)((wm + r0) * AS2 + col) * 2;
                hi = split_pack(v0, v1, lo);
                *(uint32_t*)(smem + OFF_AH + offA) = hi;
                *(uint32_t*)(smem + OFF_AL + offA) = lo;
                uint32_t offB = (uint32_t)((wm + r0 + 8) * AS2 + col) * 2;
                hi = split_pack(v2, v3, lo);
                *(uint32_t*)(smem + OFF_AH + offB) = hi;
                *(uint32_t*)(smem + OFF_AL + offB) = lo;
            }
        }

        // ---- prefetch next tile (overlaps GEMM2) ----
        {
            int tn = t + NCTA;
            if (tn < NT) {
                int bn = tn >> 8, remn = tn & 255, hon = remn >> 1, wo0n = (remn & 1) * 64;
                const float* xb = x + (size_t)bn * CC * HH * WWID;
                int rw[3], cl[3];
                #pragma unroll
                for (int kk = 0; kk < 3; kk++) {
                    rw[kk] = refl(2 * hon + kk - 1, HH) * WWID;
                    cl[kk] = refl(2 * (wo0n + pos) + kk - 1, WWID);
                }
                #pragma unroll
                for (int i = 0; i < 36; i++) {
                    int p = pb + i;
                    int c = p / 9, rr = p - c * 9;
                    int kh = rr / 3, kw = rr - kh * 3;
                    xv[i] = __ldg(&xb[c * (HH * WWID) + rw[kh] + cl[kw]]);
                }
            }
        }
        __syncthreads();   // A2 visible

        // ---- GEMM2: D2[64 x 144] ----
        float d2[9][4];
        #pragma unroll
        for (int nj = 0; nj < 9; nj++)
            #pragma unroll
            for (int p = 0; p < 4; p++) d2[nj][p] = 0.f;
        {
            uint32_t pA = sb + OFF_AH + (uint32_t)(arow * AS2 + khalf) * 2;
            uint32_t pB[4], pS;
            #pragma unroll
            for (int np = 0; np < 4; np++)
                pB[np] = sb + OFF_B2H + (uint32_t)((wn * 72 + np * 16 + (g & 1) * 8 + r) * AS2 + khalf) * 2;
            {
                const int g2 = (lid >> 3) & 1;
                pS = sb + OFF_B2H + (uint32_t)((wn * 72 + 64 + r) * AS2 + g2 * 8) * 2;
            }
            uint32_t a[4], bA[4][4], bB[4][4], sA[2], sB[2];
            #pragma unroll
            for (int ks = 0; ks < 8; ks++) {
                const uint32_t ko = ks * 32;
                ldsm4(a, pA + ko);
                #pragma unroll
                for (int np = 0; np < 4; np++) ldsm4(bA[np], pB[np] + ko);
                ldsm2(sA, pS + ko);
                #pragma unroll
                for (int np = 0; np < 4; np++) {
                    mma_bf16(d2[np * 2],     a, bA[np][0], bA[np][2]);
                    mma_bf16(d2[np * 2 + 1], a, bA[np][1], bA[np][3]);
                }
                mma_bf16(d2[8], a, sA[0], sA[1]);
                #pragma unroll
                for (int np = 0; np < 4; np++) ldsm4(bB[np], pB[np] + DB2 + ko);
                ldsm2(sB, pS + DB2 + ko);
                #pragma unroll
                for (int np = 0; np < 4; np++) {
                    mma_bf16(d2[np * 2],     a, bB[np][0], bB[np][2]);
                    mma_bf16(d2[np * 2 + 1], a, bB[np][1], bB[np][3]);
                }
                mma_bf16(d2[8], a, sB[0], sB[1]);
                ldsm4(a, pA + DA + ko);
                #pragma unroll
                for (int np = 0; np < 4; np++) {
                    mma_bf16(d2[np * 2],     a, bA[np][0], bA[np][2]);
                    mma_bf16(d2[np * 2 + 1], a, bA[np][1], bA[np][3]);
                }
                mma_bf16(d2[8], a, sA[0], sA[1]);
            }
        }

        // ---- epi2: D2 + b2 -> g_outp ----
        {
            const int r0 = lid >> 2;
            const int c0 = (lid & 3) * 2;
            float* ob = g_outp + ((size_t)b * LL + (size_t)ho * 128 + wo0) * PP;
            #pragma unroll
            for (int nj = 0; nj < 9; nj++) {
                const int col = wn * 72 + nj * 8 + c0;
                const float bb0 = b2s[col], bb1 = b2s[col + 1];
                float2 v0 = make_float2(d2[nj][0] + bb0, d2[nj][1] + bb1);
                float2 v1 = make_float2(d2[nj][2] + bb0, d2[nj][3] + bb1);
                *(float2*)&ob[(size_t)(wm + r0) * PP + col]     = v0;
                *(float2*)&ob[(size_t)(wm + r0 + 8) * PP + col] = v1;
            }
        }
    }
}

// ---------------------------------------------------------------------------
// Kernel B: gather-fold + normalize + channel mix + softmax + modulate
// ---------------------------------------------------------------------------
__global__ __launch_bounds__(256)
void fold_softmax_kernel(const float* __restrict__ Wc, const float* __restrict__ bc,
                         float* __restrict__ out) {
    __shared__ float sWc[256];
    __shared__ float sbc[16];
    int tid = threadIdx.x;
    sWc[tid] = Wc[tid];
    if (tid < 16) sbc[tid] = bc[tid];
    __syncthreads();

    const int b = blockIdx.x >> 8;
    const int i = (blockIdx.x & 255) + 1;
    const int j = tid + 1;

    int khA[2], hoA[2], nh = 0;
    #pragma unroll
    for (int kh = 0; kh < 3; kh++) {
        int t = i - kh;
        if (t >= 0 && t <= 254 && !(t & 1)) { khA[nh] = kh; hoA[nh] = t >> 1; nh++; }
    }
    int kwA[2], woA[2], nw = 0;
    #pragma unroll
    for (int kw = 0; kw < 3; kw++) {
        int t = j - kw;
        if (t >= 0 && t <= 254 && !(t & 1)) { kwA[nw] = kw; woA[nw] = t >> 1; nw++; }
    }

    float nrm[16];
    #pragma unroll
    for (int c = 0; c < 16; c++) nrm[c] = 0.f;

    for (int a = 0; a < nh; a++)
        for (int d = 0; d < nw; d++) {
            const float* rec = g_outp
                + ((size_t)b * LL + hoA[a] * 128 + woA[d]) * PP
                + khA[a] * 3 + kwA[d];
            #pragma unroll
            for (int c = 0; c < 16; c++) nrm[c] += rec[c * 9];
        }

    const float inv = 1.f / ((float)(nh * nw) + 1e-6f);
    #pragma unroll
    for (int c = 0; c < 16; c++) nrm[c] *= inv;

    float logit[16];
    #pragma unroll
    for (int o = 0; o < 16; o++) {
        float s = sbc[o];
        #pragma unroll
        for (int c = 0; c < 16; c++) s += sWc[o * 16 + c] * nrm[c];
        logit[o] = s;
    }
    float m = logit[0];
    #pragma unroll
    for (int o = 1; o < 16; o++) m = fmaxf(m, logit[o]);
    float e[16], sum = 0.f;
    #pragma unroll
    for (int o = 0; o < 16; o++) { e[o] = __expf(logit[o] - m); sum += e[o]; }
    const float rs = 1.f / sum;

    float* ob = out + (size_t)b * CC * HH * WWID + (size_t)(i - 1) * WWID + (j - 1);
    #pragma unroll
    for (int c = 0; c < 16; c++) ob[(size_t)c * HH * WWID] = nrm[c] * e[c] * rs;
}

// ---------------------------------------------------------------------------
extern "C" void kernel_launch(void* const* d_in, const int* in_sizes, int n_in,
                              void* d_out, int out_size) {
    const float* x  = (const float*)d_in[0];
    const float* W1 = (const float*)d_in[1];
    const float* b1 = (const float*)d_in[2];
    const float* W2 = (const float*)d_in[3];
    const float* b2 = (const float*)d_in[4];
    const float* Wc = (const float*)d_in[5];
    const float* bc = (const float*)d_in[6];
    float* out = (float*)d_out;

    cudaFuncSetAttribute(mlp_persist, cudaFuncAttributeMaxDynamicSharedMemorySize, SMEM_TOT);

    mlp_persist<<<NCTA, 256, SMEM_TOT>>>(x, W1, b1, W2, b2);
    fold_softmax_kernel<<<BB * 256, 256>>>(Wc, bc, out);
}

// round 6
// speedup vs baseline: 4.2100x; 1.1610x over previous
#include <cuda_runtime.h>
#include <cuda_bf16.h>
#include <cstdint>

#define BB   32
#define CC   16
#define HH   256
#define WWID 256
#define PP   144
#define HID  128
#define LL   16384
#define NT   8192      // tiles: B * 128 ho * 2 halves
#define NCTA 152

// Scratch for out_p, layout (B, P, L) fp32 = 302 MB
__device__ float g_outp[(size_t)BB * PP * LL];

// ---------------- smem byte offsets ----------------
#define OFF_B1H 0
#define OFF_B1L 38912              // 128 x 152 x 2B
#define OFF_B2H 77824
#define OFF_B2L 116992             // 144 x 136 x 2B
#define OFF_AH  156160             // 64 x 152 x 2B (A1) / 64 x 136 x 2B (A2)
#define OFF_AL  175616
#define OFF_b1  195072
#define OFF_b2  195584
#define SMEM_TOT 196160
#define AS1 152                    // 304B rows: 19*16B -> conflict-free ldmatrix
#define AS2 136                    // 272B rows: 17*16B
#define DB1 38912                  // hi->lo delta, B1
#define DB2 39168                  // hi->lo delta, B2
#define DA  19456                  // hi->lo delta, A

// ---------------- helpers ----------------
__device__ __forceinline__ uint32_t smem_u32(const void* p) {
    uint32_t a;
    asm("{ .reg .u64 t; cvta.to.shared.u64 t, %1; cvt.u32.u64 %0, t; }" : "=r"(a) : "l"(p));
    return a;
}
__device__ __forceinline__ void ldsm4(uint32_t* r, uint32_t a) {
    asm volatile("ldmatrix.sync.aligned.m8n8.x4.shared.b16 {%0,%1,%2,%3}, [%4];"
                 : "=r"(r[0]), "=r"(r[1]), "=r"(r[2]), "=r"(r[3]) : "r"(a));
}
__device__ __forceinline__ void ldsm2(uint32_t* r, uint32_t a) {
    asm volatile("ldmatrix.sync.aligned.m8n8.x2.shared.b16 {%0,%1}, [%2];"
                 : "=r"(r[0]), "=r"(r[1]) : "r"(a));
}
__device__ __forceinline__ void mma_bf16(float* d, const uint32_t* a, uint32_t b0, uint32_t b1) {
    asm volatile("mma.sync.aligned.m16n8k16.row.col.f32.bf16.bf16.f32 "
                 "{%0,%1,%2,%3}, {%4,%5,%6,%7}, {%8,%9}, {%0,%1,%2,%3};"
                 : "+f"(d[0]), "+f"(d[1]), "+f"(d[2]), "+f"(d[3])
                 : "r"(a[0]), "r"(a[1]), "r"(a[2]), "r"(a[3]), "r"(b0), "r"(b1));
}
__device__ __forceinline__ uint32_t split_pack(float v0, float v1, uint32_t& lo) {
    __nv_bfloat16 h0 = __float2bfloat16(v0);
    __nv_bfloat16 h1 = __float2bfloat16(v1);
    __nv_bfloat16 l0 = __float2bfloat16(v0 - __bfloat162float(h0));
    __nv_bfloat16 l1 = __float2bfloat16(v1 - __bfloat162float(h1));
    lo = (uint32_t)*(uint16_t*)&l0 | ((uint32_t)*(uint16_t*)&l1 << 16);
    return (uint32_t)*(uint16_t*)&h0 | ((uint32_t)*(uint16_t*)&h1 << 16);
}
__device__ __forceinline__ void split_sts(char* hi_base, uint32_t off, uint32_t lodelta, float v) {
    __nv_bfloat16 h = __float2bfloat16(v);
    __nv_bfloat16 l = __float2bfloat16(v - __bfloat162float(h));
    *(uint16_t*)(hi_base + off) = *(uint16_t*)&h;
    *(uint16_t*)(hi_base + lodelta + off) = *(uint16_t*)&l;
}
__device__ __forceinline__ int refl(int v, int n) {
    return (v < 0) ? -v : ((v >= n) ? 2 * n - 2 - v : v);
}

// ---------------------------------------------------------------------------
// Persistent MLP kernel. grid = NCTA, 256 threads. Weights staged once.
// Tile = 64 positions (b, ho, half). Output layout (B, P, L).
// ---------------------------------------------------------------------------
__global__ __launch_bounds__(256, 1)
void mlp_persist(const float* __restrict__ x, const float* __restrict__ W1,
                 const float* __restrict__ b1, const float* __restrict__ W2,
                 const float* __restrict__ b2) {
    extern __shared__ char smem[];
    const uint32_t sb = smem_u32(smem);
    const int tid = threadIdx.x;
    const int wid = tid >> 5, lid = tid & 31;

    float* b1s = (float*)(smem + OFF_b1);
    float* b2s = (float*)(smem + OFF_b2);
    if (tid < 128) b1s[tid] = b1[tid];
    if (tid < 144) b2s[tid] = b2[tid];

    // ---- stage W1^T and W2^T (split) ONCE ----
    #pragma unroll 4
    for (int i = 0; i < 72; i++) {
        int e = i * 256 + tid;               // e = k*128 + n
        int k = e >> 7, n = e & 127;
        split_sts(smem + OFF_B1H, (uint32_t)(n * AS1 + k) * 2, DB1, __ldg(&W1[e]));
    }
    #pragma unroll 4
    for (int i = 0; i < 72; i++) {
        int e = i * 256 + tid;               // e = k*144 + n
        int k = e / 144, n = e - k * 144;
        split_sts(smem + OFF_B2H, (uint32_t)(n * AS2 + k) * 2, DB2, __ldg(&W2[e]));
    }

    // warp tiling constants
    const int wm = (wid & 3) * 16;
    const int wn = wid >> 2;
    const int g = lid >> 3, r = lid & 7;
    const int khalf = (g >> 1) * 8;
    const int arow = wm + (g & 1) * 8 + r;

    // gather mapping: pos = tid>>2 (64), quarter q = tid&3 -> p in [q*36, q*36+36)
    const int pos = tid >> 2;
    const int q   = tid & 3;
    const int pb  = q * 36;

    float xv[36];

    // ---- prefetch first tile ----
    {
        int t = blockIdx.x;
        int b = t >> 8, rem = t & 255, ho = rem >> 1, wo0 = (rem & 1) * 64;
        const float* xb = x + ((size_t)b * CC + q * 4) * (HH * WWID);
        int rw[3], cl[3];
        #pragma unroll
        for (int kk = 0; kk < 3; kk++) {
            rw[kk] = refl(2 * ho + kk - 1, HH) * WWID;
            cl[kk] = refl(2 * (wo0 + pos) + kk - 1, WWID);
        }
        #pragma unroll
        for (int ci = 0; ci < 4; ci++) {
            const float* xc = xb + ci * (HH * WWID);
            #pragma unroll
            for (int kh = 0; kh < 3; kh++)
                #pragma unroll
                for (int kw = 0; kw < 3; kw++)
                    xv[ci * 9 + kh * 3 + kw] = __ldg(&xc[rw[kh] + cl[kw]]);
        }
    }

    for (int t = blockIdx.x; t < NT; t += NCTA) {
        const int b = t >> 8, rem = t & 255, ho = rem >> 1, wo0 = (rem & 1) * 64;

        __syncthreads();   // prev GEMM2 done reading A buffer
        // ---- store A1 (split) ----
        #pragma unroll
        for (int i = 0; i < 18; i++) {
            uint32_t lo, hi = split_pack(xv[2 * i], xv[2 * i + 1], lo);
            uint32_t off = (uint32_t)(pos * AS1 + pb + 2 * i) * 2;
            *(uint32_t*)(smem + OFF_AH + off) = hi;
            *(uint32_t*)(smem + OFF_AL + off) = lo;
        }
        __syncthreads();

        // ---- GEMM1: D1[64 x 128] ----
        float d1[8][4];
        #pragma unroll
        for (int nj = 0; nj < 8; nj++)
            #pragma unroll
            for (int p = 0; p < 4; p++) d1[nj][p] = 0.f;
        {
            uint32_t pA = sb + OFF_AH + (uint32_t)(arow * AS1 + khalf) * 2;
            uint32_t pB[4];
            #pragma unroll
            for (int np = 0; np < 4; np++)
                pB[np] = sb + OFF_B1H + (uint32_t)((wn * 64 + np * 16 + (g & 1) * 8 + r) * AS1 + khalf) * 2;

            uint32_t a[4], bA[4][4], bB[4][4];
            #pragma unroll
            for (int ks = 0; ks < 9; ks++) {
                const uint32_t ko = ks * 32;
                ldsm4(a, pA + ko);
                #pragma unroll
                for (int np = 0; np < 4; np++) ldsm4(bA[np], pB[np] + ko);
                #pragma unroll
                for (int np = 0; np < 4; np++) {
                    mma_bf16(d1[np * 2],     a, bA[np][0], bA[np][2]);
                    mma_bf16(d1[np * 2 + 1], a, bA[np][1], bA[np][3]);
                }
                #pragma unroll
                for (int np = 0; np < 4; np++) ldsm4(bB[np], pB[np] + DB1 + ko);
                #pragma unroll
                for (int np = 0; np < 4; np++) {
                    mma_bf16(d1[np * 2],     a, bB[np][0], bB[np][2]);
                    mma_bf16(d1[np * 2 + 1], a, bB[np][1], bB[np][3]);
                }
                ldsm4(a, pA + DA + ko);
                #pragma unroll
                for (int np = 0; np < 4; np++) {
                    mma_bf16(d1[np * 2],     a, bA[np][0], bA[np][2]);
                    mma_bf16(d1[np * 2 + 1], a, bA[np][1], bA[np][3]);
                }
            }
        }
        __syncthreads();   // all warps done reading A1

        // ---- epi1: relu(D1+b1) split -> A2 (stride AS2) ----
        {
            const int r0 = lid >> 2;
            const int c0 = (lid & 3) * 2;
            #pragma unroll
            for (int nj = 0; nj < 8; nj++) {
                const int col = wn * 64 + nj * 8 + c0;
                const float bb0 = b1s[col], bb1 = b1s[col + 1];
                float v0 = d1[nj][0] + bb0; v0 = v0 > 0.f ? v0 : 0.f;
                float v1 = d1[nj][1] + bb1; v1 = v1 > 0.f ? v1 : 0.f;
                float v2 = d1[nj][2] + bb0; v2 = v2 > 0.f ? v2 : 0.f;
                float v3 = d1[nj][3] + bb1; v3 = v3 > 0.f ? v3 : 0.f;
                uint32_t lo, hi;
                uint32_t offA = (uint32_t)((wm + r0) * AS2 + col) * 2;
                hi = split_pack(v0, v1, lo);
                *(uint32_t*)(smem + OFF_AH + offA) = hi;
                *(uint32_t*)(smem + OFF_AL + offA) = lo;
                uint32_t offB = (uint32_t)((wm + r0 + 8) * AS2 + col) * 2;
                hi = split_pack(v2, v3, lo);
                *(uint32_t*)(smem + OFF_AH + offB) = hi;
                *(uint32_t*)(smem + OFF_AL + offB) = lo;
            }
        }

        // ---- prefetch next tile (overlaps GEMM2) ----
        {
            int tn = t + NCTA;
            if (tn < NT) {
                int bn = tn >> 8, remn = tn & 255, hon = remn >> 1, wo0n = (remn & 1) * 64;
                const float* xb = x + ((size_t)bn * CC + q * 4) * (HH * WWID);
                int rw[3], cl[3];
                #pragma unroll
                for (int kk = 0; kk < 3; kk++) {
                    rw[kk] = refl(2 * hon + kk - 1, HH) * WWID;
                    cl[kk] = refl(2 * (wo0n + pos) + kk - 1, WWID);
                }
                #pragma unroll
                for (int ci = 0; ci < 4; ci++) {
                    const float* xc = xb + ci * (HH * WWID);
                    #pragma unroll
                    for (int kh = 0; kh < 3; kh++)
                        #pragma unroll
                        for (int kw = 0; kw < 3; kw++)
                            xv[ci * 9 + kh * 3 + kw] = __ldg(&xc[rw[kh] + cl[kw]]);
                }
            }
        }
        __syncthreads();   // A2 visible

        // ---- GEMM2: D2[64 x 144] ----
        float d2[9][4];
        #pragma unroll
        for (int nj = 0; nj < 9; nj++)
            #pragma unroll
            for (int p = 0; p < 4; p++) d2[nj][p] = 0.f;
        {
            uint32_t pA = sb + OFF_AH + (uint32_t)(arow * AS2 + khalf) * 2;
            uint32_t pB[4], pS;
            #pragma unroll
            for (int np = 0; np < 4; np++)
                pB[np] = sb + OFF_B2H + (uint32_t)((wn * 72 + np * 16 + (g & 1) * 8 + r) * AS2 + khalf) * 2;
            {
                const int g2 = (lid >> 3) & 1;
                pS = sb + OFF_B2H + (uint32_t)((wn * 72 + 64 + r) * AS2 + g2 * 8) * 2;
            }
            uint32_t a[4], bA[4][4], bB[4][4], sA[2], sB[2];
            #pragma unroll
            for (int ks = 0; ks < 8; ks++) {
                const uint32_t ko = ks * 32;
                ldsm4(a, pA + ko);
                #pragma unroll
                for (int np = 0; np < 4; np++) ldsm4(bA[np], pB[np] + ko);
                ldsm2(sA, pS + ko);
                #pragma unroll
                for (int np = 0; np < 4; np++) {
                    mma_bf16(d2[np * 2],     a, bA[np][0], bA[np][2]);
                    mma_bf16(d2[np * 2 + 1], a, bA[np][1], bA[np][3]);
                }
                mma_bf16(d2[8], a, sA[0], sA[1]);
                #pragma unroll
                for (int np = 0; np < 4; np++) ldsm4(bB[np], pB[np] + DB2 + ko);
                ldsm2(sB, pS + DB2 + ko);
                #pragma unroll
                for (int np = 0; np < 4; np++) {
                    mma_bf16(d2[np * 2],     a, bB[np][0], bB[np][2]);
                    mma_bf16(d2[np * 2 + 1], a, bB[np][1], bB[np][3]);
                }
                mma_bf16(d2[8], a, sB[0], sB[1]);
                ldsm4(a, pA + DA + ko);
                #pragma unroll
                for (int np = 0; np < 4; np++) {
                    mma_bf16(d2[np * 2],     a, bA[np][0], bA[np][2]);
                    mma_bf16(d2[np * 2 + 1], a, bA[np][1], bA[np][3]);
                }
                mma_bf16(d2[8], a, sA[0], sA[1]);
            }
        }

        // ---- epi2: D2 + b2 -> g_outp[b][col][pos] (coalesced 32B runs) ----
        {
            const int r0 = lid >> 2;
            const int c0 = (lid & 3) * 2;
            float* ob = g_outp + (size_t)b * PP * LL + (size_t)ho * 128 + wo0;
            const int posA = wm + r0;
            const int posB = posA + 8;
            #pragma unroll
            for (int nj = 0; nj < 9; nj++) {
                const int col = wn * 72 + nj * 8 + c0;
                const float bb0 = b2s[col], bb1 = b2s[col + 1];
                float* c0p = ob + (size_t)col * LL;
                float* c1p = c0p + LL;
                c0p[posA] = d2[nj][0] + bb0;
                c1p[posA] = d2[nj][1] + bb1;
                c0p[posB] = d2[nj][2] + bb0;
                c1p[posB] = d2[nj][3] + bb1;
            }
        }
    }
}

// ---------------------------------------------------------------------------
// Kernel B: gather-fold + normalize + channel mix + softmax + modulate
// Reads (B, P, L) layout -> lane-consecutive wo -> coalesced.
// ---------------------------------------------------------------------------
__global__ __launch_bounds__(256)
void fold_softmax_kernel(const float* __restrict__ Wc, const float* __restrict__ bc,
                         float* __restrict__ out) {
    __shared__ float sWc[256];
    __shared__ float sbc[16];
    int tid = threadIdx.x;
    sWc[tid] = Wc[tid];
    if (tid < 16) sbc[tid] = bc[tid];
    __syncthreads();

    const int b = blockIdx.x >> 8;
    const int i = (blockIdx.x & 255) + 1;   // padded row in [1,256]
    const int j = tid + 1;                  // padded col in [1,256]

    int khA[2], hoA[2], nh = 0;
    #pragma unroll
    for (int kh = 0; kh < 3; kh++) {
        int t = i - kh;
        if (t >= 0 && t <= 254 && !(t & 1)) { khA[nh] = kh; hoA[nh] = t >> 1; nh++; }
    }
    int kwA[2], woA[2], nw = 0;
    #pragma unroll
    for (int kw = 0; kw < 3; kw++) {
        int t = j - kw;
        if (t >= 0 && t <= 254 && !(t & 1)) { kwA[nw] = kw; woA[nw] = t >> 1; nw++; }
    }

    float nrm[16];
    #pragma unroll
    for (int c = 0; c < 16; c++) nrm[c] = 0.f;

    const float* gb = g_outp + (size_t)b * PP * LL;
    for (int a = 0; a < nh; a++)
        for (int d = 0; d < nw; d++) {
            const float* rec = gb + (size_t)(khA[a] * 3 + kwA[d]) * LL
                             + hoA[a] * 128 + woA[d];
            #pragma unroll
            for (int c = 0; c < 16; c++) nrm[c] += rec[(size_t)c * 9 * LL];
        }

    const float inv = 1.f / ((float)(nh * nw) + 1e-6f);
    #pragma unroll
    for (int c = 0; c < 16; c++) nrm[c] *= inv;

    float logit[16];
    #pragma unroll
    for (int o = 0; o < 16; o++) {
        float s = sbc[o];
        #pragma unroll
        for (int c = 0; c < 16; c++) s += sWc[o * 16 + c] * nrm[c];
        logit[o] = s;
    }
    float m = logit[0];
    #pragma unroll
    for (int o = 1; o < 16; o++) m = fmaxf(m, logit[o]);
    float e[16], sum = 0.f;
    #pragma unroll
    for (int o = 0; o < 16; o++) { e[o] = __expf(logit[o] - m); sum += e[o]; }
    const float rs = 1.f / sum;

    float* ob = out + (size_t)b * CC * HH * WWID + (size_t)(i - 1) * WWID + (j - 1);
    #pragma unroll
    for (int c = 0; c < 16; c++) ob[(size_t)c * HH * WWID] = nrm[c] * e[c] * rs;
}

// ---------------------------------------------------------------------------
extern "C" void kernel_launch(void* const* d_in, const int* in_sizes, int n_in,
                              void* d_out, int out_size) {
    const float* x  = (const float*)d_in[0];
    const float* W1 = (const float*)d_in[1];
    const float* b1 = (const float*)d_in[2];
    const float* W2 = (const float*)d_in[3];
    const float* b2 = (const float*)d_in[4];
    const float* Wc = (const float*)d_in[5];
    const float* bc = (const float*)d_in[6];
    float* out = (float*)d_out;

    cudaFuncSetAttribute(mlp_persist, cudaFuncAttributeMaxDynamicSharedMemorySize, SMEM_TOT);

    mlp_persist<<<NCTA, 256, SMEM_TOT>>>(x, W1, b1, W2, b2);
    fold_softmax_kernel<<<BB * 256, 256>>>(Wc, bc, out);
}